// round 1
// baseline (speedup 1.0000x reference)
#include <cuda_runtime.h>
#include <math.h>

// ---------------- scratch (static device allocations are allowed) -----------
#define NTOK 65536            // 16 * 4096
#define DIM 256
#define QKVC 768
#define HID 1024

__device__ float g_ln  [(size_t)NTOK * DIM];   // LN output (reused for LN1, LN2)
__device__ float g_qkv [(size_t)NTOK * QKVC];  // qkv projection
__device__ float g_attn[(size_t)NTOK * DIM];   // attention output (token order)
__device__ float g_mlp [(size_t)NTOK * HID];   // fc1+gelu output

// ---------------- LayerNorm: one warp per token (C=256) ---------------------
__global__ void ln_kernel(const float* __restrict__ x,
                          const float* __restrict__ g,
                          const float* __restrict__ b,
                          float* __restrict__ out) {
    int warp = (blockIdx.x * blockDim.x + threadIdx.x) >> 5;
    int lane = threadIdx.x & 31;
    if (warp >= NTOK) return;
    const float* xp = x + (size_t)warp * DIM;
    float4 v0 = *(const float4*)(xp + lane * 4);
    float4 v1 = *(const float4*)(xp + 128 + lane * 4);
    float s  = v0.x + v0.y + v0.z + v0.w + v1.x + v1.y + v1.z + v1.w;
    float ss = v0.x*v0.x + v0.y*v0.y + v0.z*v0.z + v0.w*v0.w
             + v1.x*v1.x + v1.y*v1.y + v1.z*v1.z + v1.w*v1.w;
    #pragma unroll
    for (int o = 16; o > 0; o >>= 1) {
        s  += __shfl_xor_sync(0xffffffffu, s,  o);
        ss += __shfl_xor_sync(0xffffffffu, ss, o);
    }
    float mu  = s * (1.0f / DIM);
    float var = ss * (1.0f / DIM) - mu * mu;
    float inv = rsqrtf(var + 1e-5f);
    float4 g0 = *(const float4*)(g + lane * 4);
    float4 g1 = *(const float4*)(g + 128 + lane * 4);
    float4 b0 = *(const float4*)(b + lane * 4);
    float4 b1 = *(const float4*)(b + 128 + lane * 4);
    float4 o0, o1;
    o0.x = (v0.x - mu) * inv * g0.x + b0.x;
    o0.y = (v0.y - mu) * inv * g0.y + b0.y;
    o0.z = (v0.z - mu) * inv * g0.z + b0.z;
    o0.w = (v0.w - mu) * inv * g0.w + b0.w;
    o1.x = (v1.x - mu) * inv * g1.x + b1.x;
    o1.y = (v1.y - mu) * inv * g1.y + b1.y;
    o1.z = (v1.z - mu) * inv * g1.z + b1.z;
    o1.w = (v1.w - mu) * inv * g1.w + b1.w;
    float* op = out + (size_t)warp * DIM;
    *(float4*)(op + lane * 4)       = o0;
    *(float4*)(op + 128 + lane * 4) = o1;
}

// ---------------- SGEMM 128x128x8, 8x8 microtile, 256 threads ---------------
// EPI: 0 = plain store, 2 = +bias then exact GELU, 3 = +bias +residual
#define BM 128
#define BN 128
#define BKK 8
#define TM 8
#define TN 8

__device__ __forceinline__ float gelu_exact(float v) {
    return 0.5f * v * (1.0f + erff(v * 0.70710678118654752f));
}

template<int EPI>
__global__ __launch_bounds__(256) void sgemm_kernel(
    const float* __restrict__ A, const float* __restrict__ B,
    float* __restrict__ C, int M, int N, int K,
    const float* __restrict__ bias, const float* __restrict__ res) {
    __shared__ float As[BKK][BM];
    __shared__ float Bs[BKK][BN];
    int tid = threadIdx.x;
    int block_row = blockIdx.y * BM;
    int block_col = blockIdx.x * BN;
    int tr = tid >> 4;          // 0..15
    int tc = tid & 15;          // 0..15
    int a_row  = tid >> 1;          // 0..127
    int a_col4 = (tid & 1) * 4;     // 0 or 4
    int b_row  = tid >> 5;          // 0..7
    int b_col4 = (tid & 31) * 4;    // 0..124

    float acc[TM][TN];
    #pragma unroll
    for (int i = 0; i < TM; i++)
        #pragma unroll
        for (int j = 0; j < TN; j++) acc[i][j] = 0.0f;

    const float* Aptr = A + (size_t)(block_row + a_row) * K + a_col4;
    const float* Bptr = B + (size_t)b_row * N + block_col + b_col4;

    for (int k0 = 0; k0 < K; k0 += BKK) {
        float4 av = *(const float4*)(Aptr + k0);
        float4 bv = *(const float4*)(Bptr + (size_t)k0 * N);
        As[a_col4 + 0][a_row] = av.x;
        As[a_col4 + 1][a_row] = av.y;
        As[a_col4 + 2][a_row] = av.z;
        As[a_col4 + 3][a_row] = av.w;
        *(float4*)&Bs[b_row][b_col4] = bv;
        __syncthreads();
        #pragma unroll
        for (int k = 0; k < BKK; k++) {
            float4 ra0 = *(const float4*)&As[k][tr * TM];
            float4 ra1 = *(const float4*)&As[k][tr * TM + 4];
            float4 rb0 = *(const float4*)&Bs[k][tc * TN];
            float4 rb1 = *(const float4*)&Bs[k][tc * TN + 4];
            float ra[TM] = {ra0.x, ra0.y, ra0.z, ra0.w, ra1.x, ra1.y, ra1.z, ra1.w};
            float rb[TN] = {rb0.x, rb0.y, rb0.z, rb0.w, rb1.x, rb1.y, rb1.z, rb1.w};
            #pragma unroll
            for (int i = 0; i < TM; i++)
                #pragma unroll
                for (int j = 0; j < TN; j++)
                    acc[i][j] = fmaf(ra[i], rb[j], acc[i][j]);
        }
        __syncthreads();
    }

    #pragma unroll
    for (int i = 0; i < TM; i++) {
        size_t row = (size_t)(block_row + tr * TM + i);
        #pragma unroll
        for (int j = 0; j < TN; j += 4) {
            int col = block_col + tc * TN + j;
            float4 v = make_float4(acc[i][j], acc[i][j+1], acc[i][j+2], acc[i][j+3]);
            if (EPI >= 1) {
                v.x += bias[col + 0]; v.y += bias[col + 1];
                v.z += bias[col + 2]; v.w += bias[col + 3];
            }
            if (EPI == 2) {
                v.x = gelu_exact(v.x); v.y = gelu_exact(v.y);
                v.z = gelu_exact(v.z); v.w = gelu_exact(v.w);
            }
            if (EPI == 3) {
                float4 r = *(const float4*)&res[row * N + col];
                v.x += r.x; v.y += r.y; v.z += r.z; v.w += r.w;
            }
            *(float4*)&C[row * N + col] = v;
        }
    }
}

// ---------------- windowed attention: block = (window, head), 64 threads ----
// qkv layout per token: [3][8 heads][32], window = 8x8 tokens, N=64
__global__ __launch_bounds__(64) void attn_kernel(
    const float* __restrict__ qkv,
    const float* __restrict__ relb,   // [(2*8-1)^2 = 225][8]
    float* __restrict__ out) {
    int wi = blockIdx.x;   // 0..1023
    int h  = blockIdx.y;   // 0..7
    int n  = threadIdx.x;  // 0..63 (query row)

    __shared__ float sk[64][33];
    __shared__ float sv[64][33];

    int b = wi >> 6, wrem = wi & 63;
    int wh = wrem >> 3, ww = wrem & 7;
    int ih = n >> 3,  iw = n & 7;
    int gt = b * 4096 + (wh * 8 + ih) * 64 + (ww * 8 + iw);

    const float* base = qkv + (size_t)gt * QKVC + h * 32;
    const float scale = 0.17677669529663688f;   // 32^-0.5

    float q[32];
    #pragma unroll
    for (int i = 0; i < 8; i++) {
        float4 tq = ((const float4*)(base      ))[i];
        float4 tk = ((const float4*)(base + 256))[i];
        float4 tv = ((const float4*)(base + 512))[i];
        q[4*i+0] = tq.x * scale; q[4*i+1] = tq.y * scale;
        q[4*i+2] = tq.z * scale; q[4*i+3] = tq.w * scale;
        sk[n][4*i+0] = tk.x; sk[n][4*i+1] = tk.y;
        sk[n][4*i+2] = tk.z; sk[n][4*i+3] = tk.w;
        sv[n][4*i+0] = tv.x; sv[n][4*i+1] = tv.y;
        sv[n][4*i+2] = tv.z; sv[n][4*i+3] = tv.w;
    }
    __syncthreads();

    float mx = -1e30f, sum = 0.0f;
    float o[32];
    #pragma unroll
    for (int d = 0; d < 32; d++) o[d] = 0.0f;

    #pragma unroll 2
    for (int m = 0; m < 64; m++) {
        int jh = m >> 3, jw = m & 7;
        int ridx = (ih - jh + 7) * 15 + (iw - jw + 7);
        float sc = __ldg(&relb[ridx * 8 + h]);
        #pragma unroll
        for (int d = 0; d < 32; d++) sc = fmaf(q[d], sk[m][d], sc);
        float nm = fmaxf(mx, sc);
        float corr = __expf(mx - nm);
        float p = __expf(sc - nm);
        sum = sum * corr + p;
        #pragma unroll
        for (int d = 0; d < 32; d++) o[d] = fmaf(o[d], corr, p * sv[m][d]);
        mx = nm;
    }
    float inv = 1.0f / sum;
    float* op = out + (size_t)gt * DIM + h * 32;
    #pragma unroll
    for (int i = 0; i < 8; i++) {
        float4 v = make_float4(o[4*i] * inv, o[4*i+1] * inv, o[4*i+2] * inv, o[4*i+3] * inv);
        ((float4*)op)[i] = v;
    }
}

// ---------------- launch ----------------------------------------------------
extern "C" void kernel_launch(void* const* d_in, const int* in_sizes, int n_in,
                              void* d_out, int out_size) {
    const float* x      = (const float*)d_in[0];
    // d_in[1]=H, d_in[2]=W (always 64)
    const float* ln1_g  = (const float*)d_in[3];
    const float* ln1_b  = (const float*)d_in[4];
    const float* qkv_w  = (const float*)d_in[5];
    const float* proj_w = (const float*)d_in[6];
    const float* proj_b = (const float*)d_in[7];
    const float* relb   = (const float*)d_in[8];
    const float* ln2_g  = (const float*)d_in[9];
    const float* ln2_b  = (const float*)d_in[10];
    const float* fc1_w  = (const float*)d_in[11];
    const float* fc1_b  = (const float*)d_in[12];
    const float* fc2_w  = (const float*)d_in[13];
    const float* fc2_b  = (const float*)d_in[14];
    float* out = (float*)d_out;

    float *p_ln, *p_qkv, *p_attn, *p_mlp;
    cudaGetSymbolAddress((void**)&p_ln,   g_ln);
    cudaGetSymbolAddress((void**)&p_qkv,  g_qkv);
    cudaGetSymbolAddress((void**)&p_attn, g_attn);
    cudaGetSymbolAddress((void**)&p_mlp,  g_mlp);

    // 1. LN1
    ln_kernel<<<NTOK / 8, 256>>>(x, ln1_g, ln1_b, p_ln);
    // 2. QKV gemm: [65536,256] @ [256,768]
    sgemm_kernel<0><<<dim3(QKVC / BN, NTOK / BM), 256>>>(
        p_ln, qkv_w, p_qkv, NTOK, QKVC, DIM, nullptr, nullptr);
    // 3. window attention
    attn_kernel<<<dim3(1024, 8), 64>>>(p_qkv, relb, p_attn);
    // 4. proj + bias + residual(x) -> out
    sgemm_kernel<3><<<dim3(DIM / BN, NTOK / BM), 256>>>(
        p_attn, proj_w, out, NTOK, DIM, DIM, proj_b, x);
    // 5. LN2 on out
    ln_kernel<<<NTOK / 8, 256>>>(out, ln2_g, ln2_b, p_ln);
    // 6. fc1 + bias + gelu
    sgemm_kernel<2><<<dim3(HID / BN, NTOK / BM), 256>>>(
        p_ln, fc1_w, p_mlp, NTOK, HID, DIM, fc1_b, nullptr);
    // 7. fc2 + bias + residual(out) -> out (in-place, one thread per element)
    sgemm_kernel<3><<<dim3(DIM / BN, NTOK / BM), 256>>>(
        p_mlp, fc2_w, out, NTOK, DIM, HID, fc2_b, out);
}

// round 3
// speedup vs baseline: 2.4589x; 2.4589x over previous
#include <cuda_runtime.h>
#include <math.h>
#include <stdint.h>

#define NTOK 65536            // 16 * 4096
#define DIM 256
#define QKVC 768
#define HID 1024

// ---------------- scratch ----------------------------------------------------
__device__ float g_ln  [(size_t)NTOK * DIM];
__device__ float g_qkv [(size_t)NTOK * QKVC];
__device__ float g_attn[(size_t)NTOK * DIM];
__device__ float g_mlp [(size_t)NTOK * HID];
// transposed weights: qkv[768][256], proj[256][256], fc1[1024][256], fc2[256][1024]
#define WT_QKV 0
#define WT_PROJ (QKVC * DIM)
#define WT_FC1  (WT_PROJ + DIM * DIM)
#define WT_FC2  (WT_FC1 + HID * DIM)
__device__ float g_wt[WT_FC2 + DIM * HID];

// ---------------- helpers -----------------------------------------------------
__device__ __forceinline__ uint32_t smem_u32(const void* p) {
    return (uint32_t)__cvta_generic_to_shared((void*)p);
}
__device__ __forceinline__ void cp_async16(uint32_t dst, const void* src) {
    asm volatile("cp.async.cg.shared.global [%0], [%1], 16;" :: "r"(dst), "l"(src));
}
__device__ __forceinline__ float gelu_exact(float v) {
    return 0.5f * v * (1.0f + erff(v * 0.70710678118654752f));
}
__device__ __forceinline__ void mma_tf32(float* c, const uint32_t* a, const uint32_t* b) {
    asm volatile(
        "mma.sync.aligned.m16n8k8.row.col.f32.tf32.tf32.f32 "
        "{%0,%1,%2,%3}, {%4,%5,%6,%7}, {%8,%9}, {%0,%1,%2,%3};"
        : "+f"(c[0]), "+f"(c[1]), "+f"(c[2]), "+f"(c[3])
        : "r"(a[0]), "r"(a[1]), "r"(a[2]), "r"(a[3]), "r"(b[0]), "r"(b[1]));
}

// ---------------- transpose [R][C] -> [C][R] ---------------------------------
__global__ void transpose_kernel(const float* __restrict__ in, float* __restrict__ out,
                                 int R, int C) {
    __shared__ float t[32][33];
    int bx = blockIdx.x * 32, by = blockIdx.y * 32;
    int x = threadIdx.x, y = threadIdx.y;
    #pragma unroll
    for (int j = 0; j < 32; j += 8)
        t[y + j][x] = in[(size_t)(by + y + j) * C + bx + x];
    __syncthreads();
    #pragma unroll
    for (int j = 0; j < 32; j += 8)
        out[(size_t)(bx + y + j) * R + by + x] = t[x][y + j];
}

// ---------------- LayerNorm: one warp per token (C=256) ----------------------
__global__ void ln_kernel(const float* __restrict__ x,
                          const float* __restrict__ g,
                          const float* __restrict__ b,
                          float* __restrict__ out) {
    int warp = (blockIdx.x * blockDim.x + threadIdx.x) >> 5;
    int lane = threadIdx.x & 31;
    if (warp >= NTOK) return;
    const float* xp = x + (size_t)warp * DIM;
    float4 v0 = *(const float4*)(xp + lane * 4);
    float4 v1 = *(const float4*)(xp + 128 + lane * 4);
    float s  = v0.x + v0.y + v0.z + v0.w + v1.x + v1.y + v1.z + v1.w;
    float ss = v0.x*v0.x + v0.y*v0.y + v0.z*v0.z + v0.w*v0.w
             + v1.x*v1.x + v1.y*v1.y + v1.z*v1.z + v1.w*v1.w;
    #pragma unroll
    for (int o = 16; o > 0; o >>= 1) {
        s  += __shfl_xor_sync(0xffffffffu, s,  o);
        ss += __shfl_xor_sync(0xffffffffu, ss, o);
    }
    float mu  = s * (1.0f / DIM);
    float var = ss * (1.0f / DIM) - mu * mu;
    float inv = rsqrtf(var + 1e-5f);
    float4 g0 = *(const float4*)(g + lane * 4);
    float4 g1 = *(const float4*)(g + 128 + lane * 4);
    float4 b0 = *(const float4*)(b + lane * 4);
    float4 b1 = *(const float4*)(b + 128 + lane * 4);
    float4 o0, o1;
    o0.x = (v0.x - mu) * inv * g0.x + b0.x;
    o0.y = (v0.y - mu) * inv * g0.y + b0.y;
    o0.z = (v0.z - mu) * inv * g0.z + b0.z;
    o0.w = (v0.w - mu) * inv * g0.w + b0.w;
    o1.x = (v1.x - mu) * inv * g1.x + b1.x;
    o1.y = (v1.y - mu) * inv * g1.y + b1.y;
    o1.z = (v1.z - mu) * inv * g1.z + b1.z;
    o1.w = (v1.w - mu) * inv * g1.w + b1.w;
    float* op = out + (size_t)warp * DIM;
    *(float4*)(op + lane * 4)       = o0;
    *(float4*)(op + 128 + lane * 4) = o1;
}

// ---------------- tf32 mma.sync GEMM ------------------------------------------
// C[M][N] = A[M][K] @ Bt[N][K]^T.  Block 128x128, K-chunk 32, double-buffered
// cp.async staging.  8 warps: 4(M) x 2(N), warp tile 32x64 = 2x8 m16n8k8 atoms.
// EPI: 0 plain, 2 +bias+gelu, 3 +bias+residual.
#define ASTRIDE 36                       // floats per SMEM row (pad: banks bijective)
#define STAGE_F (128 * ASTRIDE)          // floats per matrix per stage
#define GSM_TOTAL (2 * 2 * STAGE_F * 4)  // 2 stages * (A+B) * bytes = 73728

template<int EPI>
__global__ __launch_bounds__(256)
void tc_gemm(const float* __restrict__ A, const float* __restrict__ Bt,
             float* __restrict__ C, int K, int N,
             const float* __restrict__ bias, const float* __restrict__ res) {
    extern __shared__ float sm[];
    // layout: [stage0 A][stage0 B][stage1 A][stage1 B]
    int tid = threadIdx.x;
    int lane = tid & 31, wid = tid >> 5;
    int warp_m = wid & 3;        // 0..3
    int warp_n = wid >> 2;       // 0..1
    int block_row = blockIdx.y * 128;
    int block_col = blockIdx.x * 128;

    const float* gA = A  + (size_t)block_row * K;
    const float* gB = Bt + (size_t)block_col * K;

    uint32_t smA_u[2], smB_u[2];
    smA_u[0] = smem_u32(sm);
    smB_u[0] = smem_u32(sm + STAGE_F);
    smA_u[1] = smem_u32(sm + 2 * STAGE_F);
    smB_u[1] = smem_u32(sm + 3 * STAGE_F);

    // stage chunk c into buffers s
    auto stage = [&](int c, int s) {
        int c0 = c * 32;
        #pragma unroll
        for (int it = 0; it < 4; ++it) {
            int seg = tid + it * 256;           // 0..1023
            int r = seg >> 3, c4 = (seg & 7) * 4;
            cp_async16(smA_u[s] + (uint32_t)(r * ASTRIDE + c4) * 4,
                       gA + (size_t)r * K + c0 + c4);
        }
        #pragma unroll
        for (int it = 0; it < 4; ++it) {
            int seg = tid + it * 256;
            int r = seg >> 3, c4 = (seg & 7) * 4;
            cp_async16(smB_u[s] + (uint32_t)(r * ASTRIDE + c4) * 4,
                       gB + (size_t)r * K + c0 + c4);
        }
        asm volatile("cp.async.commit_group;");
    };

    float acc[2][8][4];
    #pragma unroll
    for (int i = 0; i < 2; i++)
        #pragma unroll
        for (int j = 0; j < 8; j++)
            #pragma unroll
            for (int q = 0; q < 4; q++) acc[i][j][q] = 0.0f;

    const int nch = K >> 5;
    stage(0, 0);

    int a_base = (warp_m * 32 + (lane >> 2)) * ASTRIDE + (lane & 3);
    int b_base = (warp_n * 64 + (lane >> 2)) * ASTRIDE + (lane & 3);

    for (int c = 0; c < nch; ++c) {
        int s = c & 1;
        if (c + 1 < nch) {
            stage(c + 1, s ^ 1);
            asm volatile("cp.async.wait_group 1;");
        } else {
            asm volatile("cp.async.wait_group 0;");
        }
        __syncthreads();
        const uint32_t* As = (const uint32_t*)(sm + (size_t)s * 2 * STAGE_F);
        const uint32_t* Bs = As + STAGE_F;
        #pragma unroll
        for (int kk = 0; kk < 32; kk += 8) {
            uint32_t a[2][4];
            #pragma unroll
            for (int am = 0; am < 2; ++am) {
                int base = a_base + am * 16 * ASTRIDE + kk;
                a[am][0] = As[base];
                a[am][1] = As[base + 8 * ASTRIDE];
                a[am][2] = As[base + 4];
                a[am][3] = As[base + 8 * ASTRIDE + 4];
            }
            uint32_t b[8][2];
            #pragma unroll
            for (int bn = 0; bn < 8; ++bn) {
                int base = b_base + bn * 8 * ASTRIDE + kk;
                b[bn][0] = Bs[base];
                b[bn][1] = Bs[base + 4];
            }
            #pragma unroll
            for (int am = 0; am < 2; ++am)
                #pragma unroll
                for (int bn = 0; bn < 8; ++bn)
                    mma_tf32(acc[am][bn], a[am], b[bn]);
        }
        __syncthreads();
    }

    // epilogue: float2 stores directly from fragments
    #pragma unroll
    for (int am = 0; am < 2; ++am) {
        int row0 = block_row + warp_m * 32 + am * 16 + (lane >> 2);
        #pragma unroll
        for (int bn = 0; bn < 8; ++bn) {
            int col = block_col + warp_n * 64 + bn * 8 + 2 * (lane & 3);
            float2 v0 = make_float2(acc[am][bn][0], acc[am][bn][1]);
            float2 v1 = make_float2(acc[am][bn][2], acc[am][bn][3]);
            if (EPI >= 1) {
                float bx = bias[col], by = bias[col + 1];
                v0.x += bx; v0.y += by; v1.x += bx; v1.y += by;
            }
            if (EPI == 2) {
                v0.x = gelu_exact(v0.x); v0.y = gelu_exact(v0.y);
                v1.x = gelu_exact(v1.x); v1.y = gelu_exact(v1.y);
            }
            if (EPI == 3) {
                const float2 r0 = *(const float2*)&res[(size_t)row0 * N + col];
                const float2 r1 = *(const float2*)&res[(size_t)(row0 + 8) * N + col];
                v0.x += r0.x; v0.y += r0.y; v1.x += r1.x; v1.y += r1.y;
            }
            *(float2*)&C[(size_t)row0 * N + col]       = v0;
            *(float2*)&C[(size_t)(row0 + 8) * N + col] = v1;
        }
    }
}

// ---------------- windowed attention: block = (window, head), 64 threads -----
__global__ __launch_bounds__(64) void attn_kernel(
    const float* __restrict__ qkv,
    const float* __restrict__ relb,
    float* __restrict__ out) {
    int wi = blockIdx.x;
    int h  = blockIdx.y;
    int n  = threadIdx.x;

    __shared__ float sk[64][33];
    __shared__ float sv[64][33];

    int b = wi >> 6, wrem = wi & 63;
    int wh = wrem >> 3, ww = wrem & 7;
    int ih = n >> 3,  iw = n & 7;
    int gt = b * 4096 + (wh * 8 + ih) * 64 + (ww * 8 + iw);

    const float* base = qkv + (size_t)gt * QKVC + h * 32;
    const float scale = 0.17677669529663688f;

    float q[32];
    #pragma unroll
    for (int i = 0; i < 8; i++) {
        float4 tq = ((const float4*)(base      ))[i];
        float4 tk = ((const float4*)(base + 256))[i];
        float4 tv = ((const float4*)(base + 512))[i];
        q[4*i+0] = tq.x * scale; q[4*i+1] = tq.y * scale;
        q[4*i+2] = tq.z * scale; q[4*i+3] = tq.w * scale;
        sk[n][4*i+0] = tk.x; sk[n][4*i+1] = tk.y;
        sk[n][4*i+2] = tk.z; sk[n][4*i+3] = tk.w;
        sv[n][4*i+0] = tv.x; sv[n][4*i+1] = tv.y;
        sv[n][4*i+2] = tv.z; sv[n][4*i+3] = tv.w;
    }
    __syncthreads();

    float mx = -1e30f, sum = 0.0f;
    float o[32];
    #pragma unroll
    for (int d = 0; d < 32; d++) o[d] = 0.0f;

    #pragma unroll 2
    for (int m = 0; m < 64; m++) {
        int jh = m >> 3, jw = m & 7;
        int ridx = (ih - jh + 7) * 15 + (iw - jw + 7);
        float sc = __ldg(&relb[ridx * 8 + h]);
        #pragma unroll
        for (int d = 0; d < 32; d++) sc = fmaf(q[d], sk[m][d], sc);
        float nm = fmaxf(mx, sc);
        float corr = __expf(mx - nm);
        float p = __expf(sc - nm);
        sum = sum * corr + p;
        #pragma unroll
        for (int d = 0; d < 32; d++) o[d] = fmaf(o[d], corr, p * sv[m][d]);
        mx = nm;
    }
    float inv = 1.0f / sum;
    float* op = out + (size_t)gt * DIM + h * 32;
    #pragma unroll
    for (int i = 0; i < 8; i++) {
        float4 v = make_float4(o[4*i] * inv, o[4*i+1] * inv, o[4*i+2] * inv, o[4*i+3] * inv);
        ((float4*)op)[i] = v;
    }
}

// ---------------- launch ------------------------------------------------------
extern "C" void kernel_launch(void* const* d_in, const int* in_sizes, int n_in,
                              void* d_out, int out_size) {
    const float* x      = (const float*)d_in[0];
    const float* ln1_g  = (const float*)d_in[3];
    const float* ln1_b  = (const float*)d_in[4];
    const float* qkv_w  = (const float*)d_in[5];
    const float* proj_w = (const float*)d_in[6];
    const float* proj_b = (const float*)d_in[7];
    const float* relb   = (const float*)d_in[8];
    const float* ln2_g  = (const float*)d_in[9];
    const float* ln2_b  = (const float*)d_in[10];
    const float* fc1_w  = (const float*)d_in[11];
    const float* fc1_b  = (const float*)d_in[12];
    const float* fc2_w  = (const float*)d_in[13];
    const float* fc2_b  = (const float*)d_in[14];
    float* out = (float*)d_out;

    float *p_ln, *p_qkv, *p_attn, *p_mlp, *p_wt;
    cudaGetSymbolAddress((void**)&p_ln,   g_ln);
    cudaGetSymbolAddress((void**)&p_qkv,  g_qkv);
    cudaGetSymbolAddress((void**)&p_attn, g_attn);
    cudaGetSymbolAddress((void**)&p_mlp,  g_mlp);
    cudaGetSymbolAddress((void**)&p_wt,   g_wt);

    cudaFuncSetAttribute(tc_gemm<0>, cudaFuncAttributeMaxDynamicSharedMemorySize, GSM_TOTAL);
    cudaFuncSetAttribute(tc_gemm<2>, cudaFuncAttributeMaxDynamicSharedMemorySize, GSM_TOTAL);
    cudaFuncSetAttribute(tc_gemm<3>, cudaFuncAttributeMaxDynamicSharedMemorySize, GSM_TOTAL);

    // transpose weights to [N][K]
    transpose_kernel<<<dim3(QKVC / 32, DIM / 32), dim3(32, 8)>>>(qkv_w, p_wt + WT_QKV, DIM, QKVC);
    transpose_kernel<<<dim3(DIM / 32, DIM / 32),  dim3(32, 8)>>>(proj_w, p_wt + WT_PROJ, DIM, DIM);
    transpose_kernel<<<dim3(HID / 32, DIM / 32),  dim3(32, 8)>>>(fc1_w, p_wt + WT_FC1, DIM, HID);
    transpose_kernel<<<dim3(DIM / 32, HID / 32),  dim3(32, 8)>>>(fc2_w, p_wt + WT_FC2, HID, DIM);

    // 1. LN1
    ln_kernel<<<NTOK / 8, 256>>>(x, ln1_g, ln1_b, p_ln);
    // 2. QKV: [65536,256] @ [256,768]
    tc_gemm<0><<<dim3(QKVC / 128, NTOK / 128), 256, GSM_TOTAL>>>(
        p_ln, p_wt + WT_QKV, p_qkv, DIM, QKVC, nullptr, nullptr);
    // 3. window attention
    attn_kernel<<<dim3(1024, 8), 64>>>(p_qkv, relb, p_attn);
    // 4. proj + bias + residual(x) -> out
    tc_gemm<3><<<dim3(DIM / 128, NTOK / 128), 256, GSM_TOTAL>>>(
        p_attn, p_wt + WT_PROJ, out, DIM, DIM, proj_b, x);
    // 5. LN2
    ln_kernel<<<NTOK / 8, 256>>>(out, ln2_g, ln2_b, p_ln);
    // 6. fc1 + bias + gelu
    tc_gemm<2><<<dim3(HID / 128, NTOK / 128), 256, GSM_TOTAL>>>(
        p_ln, p_wt + WT_FC1, p_mlp, DIM, HID, fc1_b, nullptr);
    // 7. fc2 + bias + residual(out) -> out
    tc_gemm<3><<<dim3(DIM / 128, NTOK / 128), 256, GSM_TOTAL>>>(
        p_mlp, p_wt + WT_FC2, out, HID, DIM, fc2_b, out);
}

// round 4
// speedup vs baseline: 2.7993x; 1.1384x over previous
#include <cuda_runtime.h>
#include <math.h>
#include <stdint.h>

#define NTOK 65536            // 16 * 4096
#define DIM 256
#define QKVC 768
#define HID 1024

// ---------------- scratch ----------------------------------------------------
__device__ float g_ln  [(size_t)NTOK * DIM];
__device__ float g_qkv [(size_t)NTOK * QKVC];
__device__ float g_attn[(size_t)NTOK * DIM];
__device__ float g_mlp [(size_t)NTOK * HID];
#define WT_QKV 0
#define WT_PROJ (QKVC * DIM)
#define WT_FC1  (WT_PROJ + DIM * DIM)
#define WT_FC2  (WT_FC1 + HID * DIM)
__device__ float g_wt[WT_FC2 + DIM * HID];

// ---------------- helpers -----------------------------------------------------
__device__ __forceinline__ uint32_t smem_u32(const void* p) {
    return (uint32_t)__cvta_generic_to_shared((void*)p);
}
__device__ __forceinline__ void cp_async16(uint32_t dst, const void* src) {
    asm volatile("cp.async.cg.shared.global [%0], [%1], 16;" :: "r"(dst), "l"(src));
}
__device__ __forceinline__ float gelu_exact(float v) {
    return 0.5f * v * (1.0f + erff(v * 0.70710678118654752f));
}
__device__ __forceinline__ void mma_tf32(float* c, const uint32_t* a, const uint32_t* b) {
    asm volatile(
        "mma.sync.aligned.m16n8k8.row.col.f32.tf32.tf32.f32 "
        "{%0,%1,%2,%3}, {%4,%5,%6,%7}, {%8,%9}, {%0,%1,%2,%3};"
        : "+f"(c[0]), "+f"(c[1]), "+f"(c[2]), "+f"(c[3])
        : "r"(a[0]), "r"(a[1]), "r"(a[2]), "r"(a[3]), "r"(b[0]), "r"(b[1]));
}

// ---------------- transpose [R][C] -> [C][R] ---------------------------------
__global__ void transpose_kernel(const float* __restrict__ in, float* __restrict__ out,
                                 int R, int C) {
    __shared__ float t[32][33];
    int bx = blockIdx.x * 32, by = blockIdx.y * 32;
    int x = threadIdx.x, y = threadIdx.y;
    #pragma unroll
    for (int j = 0; j < 32; j += 8)
        t[y + j][x] = in[(size_t)(by + y + j) * C + bx + x];
    __syncthreads();
    #pragma unroll
    for (int j = 0; j < 32; j += 8)
        out[(size_t)(bx + y + j) * R + by + x] = t[x][y + j];
}

// ---------------- LayerNorm: one warp per token (C=256) ----------------------
__global__ void ln_kernel(const float* __restrict__ x,
                          const float* __restrict__ g,
                          const float* __restrict__ b,
                          float* __restrict__ out) {
    int warp = (blockIdx.x * blockDim.x + threadIdx.x) >> 5;
    int lane = threadIdx.x & 31;
    if (warp >= NTOK) return;
    const float* xp = x + (size_t)warp * DIM;
    float4 v0 = *(const float4*)(xp + lane * 4);
    float4 v1 = *(const float4*)(xp + 128 + lane * 4);
    float s  = v0.x + v0.y + v0.z + v0.w + v1.x + v1.y + v1.z + v1.w;
    float ss = v0.x*v0.x + v0.y*v0.y + v0.z*v0.z + v0.w*v0.w
             + v1.x*v1.x + v1.y*v1.y + v1.z*v1.z + v1.w*v1.w;
    #pragma unroll
    for (int o = 16; o > 0; o >>= 1) {
        s  += __shfl_xor_sync(0xffffffffu, s,  o);
        ss += __shfl_xor_sync(0xffffffffu, ss, o);
    }
    float mu  = s * (1.0f / DIM);
    float var = ss * (1.0f / DIM) - mu * mu;
    float inv = rsqrtf(var + 1e-5f);
    float4 g0 = *(const float4*)(g + lane * 4);
    float4 g1 = *(const float4*)(g + 128 + lane * 4);
    float4 b0 = *(const float4*)(b + lane * 4);
    float4 b1 = *(const float4*)(b + 128 + lane * 4);
    float4 o0, o1;
    o0.x = (v0.x - mu) * inv * g0.x + b0.x;
    o0.y = (v0.y - mu) * inv * g0.y + b0.y;
    o0.z = (v0.z - mu) * inv * g0.z + b0.z;
    o0.w = (v0.w - mu) * inv * g0.w + b0.w;
    o1.x = (v1.x - mu) * inv * g1.x + b1.x;
    o1.y = (v1.y - mu) * inv * g1.y + b1.y;
    o1.z = (v1.z - mu) * inv * g1.z + b1.z;
    o1.w = (v1.w - mu) * inv * g1.w + b1.w;
    float* op = out + (size_t)warp * DIM;
    *(float4*)(op + lane * 4)       = o0;
    *(float4*)(op + 128 + lane * 4) = o1;
}

// ---------------- tf32 mma.sync GEMM ------------------------------------------
#define ASTRIDE 36
#define STAGE_F (128 * ASTRIDE)
#define GSM_TOTAL (2 * 2 * STAGE_F * 4)   // 73728

template<int EPI>
__global__ __launch_bounds__(256, 2)
void tc_gemm(const float* __restrict__ A, const float* __restrict__ Bt,
             float* __restrict__ C, int K, int N,
             const float* __restrict__ bias, const float* __restrict__ res) {
    extern __shared__ float sm[];
    int tid = threadIdx.x;
    int lane = tid & 31, wid = tid >> 5;
    int warp_m = wid & 3;
    int warp_n = wid >> 2;
    int block_row = blockIdx.y * 128;
    int block_col = blockIdx.x * 128;

    const float* gA = A  + (size_t)block_row * K;
    const float* gB = Bt + (size_t)block_col * K;

    uint32_t smA_u[2], smB_u[2];
    smA_u[0] = smem_u32(sm);
    smB_u[0] = smem_u32(sm + STAGE_F);
    smA_u[1] = smem_u32(sm + 2 * STAGE_F);
    smB_u[1] = smem_u32(sm + 3 * STAGE_F);

    auto stage = [&](int c, int s) {
        int c0 = c * 32;
        #pragma unroll
        for (int it = 0; it < 4; ++it) {
            int seg = tid + it * 256;
            int r = seg >> 3, c4 = (seg & 7) * 4;
            cp_async16(smA_u[s] + (uint32_t)(r * ASTRIDE + c4) * 4,
                       gA + (size_t)r * K + c0 + c4);
        }
        #pragma unroll
        for (int it = 0; it < 4; ++it) {
            int seg = tid + it * 256;
            int r = seg >> 3, c4 = (seg & 7) * 4;
            cp_async16(smB_u[s] + (uint32_t)(r * ASTRIDE + c4) * 4,
                       gB + (size_t)r * K + c0 + c4);
        }
        asm volatile("cp.async.commit_group;");
    };

    float acc[2][8][4];
    #pragma unroll
    for (int i = 0; i < 2; i++)
        #pragma unroll
        for (int j = 0; j < 8; j++)
            #pragma unroll
            for (int q = 0; q < 4; q++) acc[i][j][q] = 0.0f;

    const int nch = K >> 5;
    stage(0, 0);

    int a_base = (warp_m * 32 + (lane >> 2)) * ASTRIDE + (lane & 3);
    int b_base = (warp_n * 64 + (lane >> 2)) * ASTRIDE + (lane & 3);

    for (int c = 0; c < nch; ++c) {
        int s = c & 1;
        if (c + 1 < nch) {
            stage(c + 1, s ^ 1);
            asm volatile("cp.async.wait_group 1;");
        } else {
            asm volatile("cp.async.wait_group 0;");
        }
        __syncthreads();
        const uint32_t* As = (const uint32_t*)(sm + (size_t)s * 2 * STAGE_F);
        const uint32_t* Bs = As + STAGE_F;
        #pragma unroll
        for (int kk = 0; kk < 32; kk += 8) {
            uint32_t a[2][4];
            #pragma unroll
            for (int am = 0; am < 2; ++am) {
                int base = a_base + am * 16 * ASTRIDE + kk;
                a[am][0] = As[base];
                a[am][1] = As[base + 8 * ASTRIDE];
                a[am][2] = As[base + 4];
                a[am][3] = As[base + 8 * ASTRIDE + 4];
            }
            uint32_t b[8][2];
            #pragma unroll
            for (int bn = 0; bn < 8; ++bn) {
                int base = b_base + bn * 8 * ASTRIDE + kk;
                b[bn][0] = Bs[base];
                b[bn][1] = Bs[base + 4];
            }
            #pragma unroll
            for (int am = 0; am < 2; ++am)
                #pragma unroll
                for (int bn = 0; bn < 8; ++bn)
                    mma_tf32(acc[am][bn], a[am], b[bn]);
        }
        __syncthreads();
    }

    #pragma unroll
    for (int am = 0; am < 2; ++am) {
        int row0 = block_row + warp_m * 32 + am * 16 + (lane >> 2);
        #pragma unroll
        for (int bn = 0; bn < 8; ++bn) {
            int col = block_col + warp_n * 64 + bn * 8 + 2 * (lane & 3);
            float2 v0 = make_float2(acc[am][bn][0], acc[am][bn][1]);
            float2 v1 = make_float2(acc[am][bn][2], acc[am][bn][3]);
            if (EPI >= 1) {
                float bx = bias[col], by = bias[col + 1];
                v0.x += bx; v0.y += by; v1.x += bx; v1.y += by;
            }
            if (EPI == 2) {
                v0.x = gelu_exact(v0.x); v0.y = gelu_exact(v0.y);
                v1.x = gelu_exact(v1.x); v1.y = gelu_exact(v1.y);
            }
            if (EPI == 3) {
                const float2 r0 = *(const float2*)&res[(size_t)row0 * N + col];
                const float2 r1 = *(const float2*)&res[(size_t)(row0 + 8) * N + col];
                v0.x += r0.x; v0.y += r0.y; v1.x += r1.x; v1.y += r1.y;
            }
            *(float2*)&C[(size_t)row0 * N + col]       = v0;
            *(float2*)&C[(size_t)(row0 + 8) * N + col] = v1;
        }
    }
}

// ---------------- windowed attention ------------------------------------------
// block = (window, head), 64 threads. Cooperative coalesced loads (one token's
// 32 contiguous floats per 8 lanes), 16B-aligned SMEM rows for LDS.128 broadcast.
__global__ __launch_bounds__(64) void attn_kernel(
    const float* __restrict__ qkv,
    const float* __restrict__ relb,
    float* __restrict__ out) {
    int wi = blockIdx.x;
    int h  = blockIdx.y;
    int n  = threadIdx.x;

    __shared__ float sq[64][36];
    __shared__ float sk[64][36];
    __shared__ float sv[64][36];

    int b = wi >> 6, wrem = wi & 63;
    int wh = wrem >> 3, ww = wrem & 7;
    int tok_row = b * 4096 + wh * 8 * 64 + ww * 8;   // token of (ih=0,iw=0)

    // cooperative load: lane group of 8 covers one token's 32 floats
    {
        int f4 = (n & 7) * 4;          // feature offset (float)
        int tsub = n >> 3;             // 0..7
        #pragma unroll
        for (int it = 0; it < 8; ++it) {
            int t = it * 8 + tsub;     // window-local token 0..63
            int ih = t >> 3, iw = t & 7;
            int gt = tok_row + ih * 64 + iw;
            const float* base = qkv + (size_t)gt * QKVC + h * 32 + f4;
            float4 tq = *(const float4*)(base);
            float4 tk = *(const float4*)(base + 256);
            float4 tv = *(const float4*)(base + 512);
            *(float4*)&sq[t][f4] = tq;
            *(float4*)&sk[t][f4] = tk;
            *(float4*)&sv[t][f4] = tv;
        }
    }
    __syncthreads();

    const float scale = 0.17677669529663688f;   // 32^-0.5
    float q[32];
    #pragma unroll
    for (int i = 0; i < 8; i++) {
        float4 v = *(const float4*)&sq[n][4 * i];
        q[4*i+0] = v.x * scale; q[4*i+1] = v.y * scale;
        q[4*i+2] = v.z * scale; q[4*i+3] = v.w * scale;
    }

    int ih = n >> 3, iw = n & 7;
    float mx = -1e30f, sum = 0.0f;
    float o[32];
    #pragma unroll
    for (int d = 0; d < 32; d++) o[d] = 0.0f;

    #pragma unroll 2
    for (int m = 0; m < 64; m++) {
        int jh = m >> 3, jw = m & 7;
        int ridx = (ih - jh + 7) * 15 + (iw - jw + 7);
        float sc = __ldg(&relb[ridx * 8 + h]);
        #pragma unroll
        for (int i = 0; i < 8; i++) {
            float4 kv = *(const float4*)&sk[m][4 * i];
            sc = fmaf(q[4*i+0], kv.x, sc);
            sc = fmaf(q[4*i+1], kv.y, sc);
            sc = fmaf(q[4*i+2], kv.z, sc);
            sc = fmaf(q[4*i+3], kv.w, sc);
        }
        float nm = fmaxf(mx, sc);
        float corr = __expf(mx - nm);
        float p = __expf(sc - nm);
        sum = sum * corr + p;
        #pragma unroll
        for (int i = 0; i < 8; i++) {
            float4 vv = *(const float4*)&sv[m][4 * i];
            o[4*i+0] = fmaf(o[4*i+0], corr, p * vv.x);
            o[4*i+1] = fmaf(o[4*i+1], corr, p * vv.y);
            o[4*i+2] = fmaf(o[4*i+2], corr, p * vv.z);
            o[4*i+3] = fmaf(o[4*i+3], corr, p * vv.w);
        }
        mx = nm;
    }
    float inv = 1.0f / sum;
    // stage output back into sq, then cooperative coalesced store
    #pragma unroll
    for (int i = 0; i < 8; i++) {
        float4 v = make_float4(o[4*i] * inv, o[4*i+1] * inv, o[4*i+2] * inv, o[4*i+3] * inv);
        *(float4*)&sq[n][4 * i] = v;
    }
    __syncthreads();
    {
        int f4 = (n & 7) * 4;
        int tsub = n >> 3;
        #pragma unroll
        for (int it = 0; it < 8; ++it) {
            int t = it * 8 + tsub;
            int th = t >> 3, tw = t & 7;
            int gt = tok_row + th * 64 + tw;
            *(float4*)(out + (size_t)gt * DIM + h * 32 + f4) = *(const float4*)&sq[t][f4];
        }
    }
}

// ---------------- launch ------------------------------------------------------
extern "C" void kernel_launch(void* const* d_in, const int* in_sizes, int n_in,
                              void* d_out, int out_size) {
    const float* x      = (const float*)d_in[0];
    const float* ln1_g  = (const float*)d_in[3];
    const float* ln1_b  = (const float*)d_in[4];
    const float* qkv_w  = (const float*)d_in[5];
    const float* proj_w = (const float*)d_in[6];
    const float* proj_b = (const float*)d_in[7];
    const float* relb   = (const float*)d_in[8];
    const float* ln2_g  = (const float*)d_in[9];
    const float* ln2_b  = (const float*)d_in[10];
    const float* fc1_w  = (const float*)d_in[11];
    const float* fc1_b  = (const float*)d_in[12];
    const float* fc2_w  = (const float*)d_in[13];
    const float* fc2_b  = (const float*)d_in[14];
    float* out = (float*)d_out;

    float *p_ln, *p_qkv, *p_attn, *p_mlp, *p_wt;
    cudaGetSymbolAddress((void**)&p_ln,   g_ln);
    cudaGetSymbolAddress((void**)&p_qkv,  g_qkv);
    cudaGetSymbolAddress((void**)&p_attn, g_attn);
    cudaGetSymbolAddress((void**)&p_mlp,  g_mlp);
    cudaGetSymbolAddress((void**)&p_wt,   g_wt);

    cudaFuncSetAttribute(tc_gemm<0>, cudaFuncAttributeMaxDynamicSharedMemorySize, GSM_TOTAL);
    cudaFuncSetAttribute(tc_gemm<2>, cudaFuncAttributeMaxDynamicSharedMemorySize, GSM_TOTAL);
    cudaFuncSetAttribute(tc_gemm<3>, cudaFuncAttributeMaxDynamicSharedMemorySize, GSM_TOTAL);

    transpose_kernel<<<dim3(QKVC / 32, DIM / 32), dim3(32, 8)>>>(qkv_w, p_wt + WT_QKV, DIM, QKVC);
    transpose_kernel<<<dim3(DIM / 32, DIM / 32),  dim3(32, 8)>>>(proj_w, p_wt + WT_PROJ, DIM, DIM);
    transpose_kernel<<<dim3(HID / 32, DIM / 32),  dim3(32, 8)>>>(fc1_w, p_wt + WT_FC1, DIM, HID);
    transpose_kernel<<<dim3(DIM / 32, HID / 32),  dim3(32, 8)>>>(fc2_w, p_wt + WT_FC2, HID, DIM);

    ln_kernel<<<NTOK / 8, 256>>>(x, ln1_g, ln1_b, p_ln);
    tc_gemm<0><<<dim3(QKVC / 128, NTOK / 128), 256, GSM_TOTAL>>>(
        p_ln, p_wt + WT_QKV, p_qkv, DIM, QKVC, nullptr, nullptr);
    attn_kernel<<<dim3(1024, 8), 64>>>(p_qkv, relb, p_attn);
    tc_gemm<3><<<dim3(DIM / 128, NTOK / 128), 256, GSM_TOTAL>>>(
        p_attn, p_wt + WT_PROJ, out, DIM, DIM, proj_b, x);
    ln_kernel<<<NTOK / 8, 256>>>(out, ln2_g, ln2_b, p_ln);
    tc_gemm<2><<<dim3(HID / 128, NTOK / 128), 256, GSM_TOTAL>>>(
        p_ln, p_wt + WT_FC1, p_mlp, DIM, HID, fc1_b, nullptr);
    tc_gemm<3><<<dim3(DIM / 128, NTOK / 128), 256, GSM_TOTAL>>>(
        p_mlp, p_wt + WT_FC2, out, HID, DIM, fc2_b, out);
}